// round 13
// baseline (speedup 1.0000x reference)
#include <cuda_runtime.h>
#include <cuda_bf16.h>
#include <cstdint>

#define NB    15
#define NWIN  64
#define NTOK  144
#define NC    192
#define NH    6
#define NL    32
#define MROWS (NB*NWIN*NTOK)   /* 138240 */
#define BIAS_E 3312

// ---------------- scratch (device globals; no allocs allowed) ----------------
__device__ float g_q[(size_t)NB*NH*NWIN*NTOK*NL];      // 106 MB (pre-scaled)
__device__ float g_k[(size_t)NB*NH*NWIN*NTOK*NL];      // 106 MB
__device__ float g_v[(size_t)NB*NH*NWIN*NTOK*NL];      // 106 MB
__device__ float g_attn[(size_t)MROWS*NC];             // 106 MB
__device__ float g_bias_t[(size_t)NWIN*NH*BIAS_E];     // 5 MB, layout (w,h,e)
__device__ __nv_bfloat162 g_bias_full[(size_t)NWIN*NH*NTOK*(NTOK/2)]; // 16 MB
__device__ __nv_bfloat162 g_mask_bf[(size_t)NB*NWIN*NTOK*(NTOK/2)];   // 40 MB

__device__ __forceinline__ uint32_t f2tf32(float x) {
    uint32_t r;
    asm("cvt.rna.tf32.f32 %0, %1;" : "=r"(r) : "f"(x));
    return r;
}

__device__ __forceinline__ void mma_tf32(float c[4], uint32_t a0, uint32_t a1,
                                         uint32_t a2, uint32_t a3,
                                         uint32_t b0, uint32_t b1) {
    asm volatile(
        "mma.sync.aligned.m16n8k8.row.col.f32.tf32.tf32.f32 "
        "{%0,%1,%2,%3}, {%4,%5,%6,%7}, {%8,%9}, {%0,%1,%2,%3};"
        : "+f"(c[0]), "+f"(c[1]), "+f"(c[2]), "+f"(c[3])
        : "r"(a0), "r"(a1), "r"(a2), "r"(a3), "r"(b0), "r"(b1));
}

// ---------------- bias table transpose: (e,w,h) -> (w,h,e) -------------------
__global__ __launch_bounds__(256) void bias_transpose_k(const float* __restrict__ bt) {
    int i = blockIdx.x * 256 + threadIdx.x;
    if (i < BIAS_E * NWIN * NH) {
        int e   = i / (NWIN * NH);
        int rem = i - e * (NWIN * NH);
        int w   = rem / NH;
        int h   = rem - w * NH;
        g_bias_t[(w * NH + h) * BIAS_E + e] = bt[i];
    }
}

// ------------- bias expansion: (w,h,e) -> dense bf16 (w,h,n,m) ---------------
__global__ __launch_bounds__(256) void bias_expand_k() {
    __shared__ int moff[NTOK];
    const int wh = blockIdx.x;              // w * NH + h
    const int t  = threadIdx.x;
    if (t < NTOK) {
        int zm = t / 72, r = t - zm * 72, hm = r / 12, wm = r - hm * 12;
        moff[t] = 1656 * zm + 138 * hm - wm;
    }
    __syncthreads();
    const float* bt = g_bias_t + (size_t)wh * BIAS_E;
    __nv_bfloat162* dst = g_bias_full + (size_t)wh * (NTOK * (NTOK/2));
    for (int i = t; i < NTOK * (NTOK/2); i += 256) {
        const int n  = i / (NTOK/2);
        const int m2 = (i - n * (NTOK/2)) * 2;
        int zn = n / 72, rn = n - zn * 72, hn = rn / 12, wn = rn - hn * 12;
        const int base = 828 * zn + 23 * hn + wn + 11;
        float v0 = __ldg(bt + base + moff[m2]);
        float v1 = __ldg(bt + base + moff[m2 + 1]);
        dst[i] = __floats2bfloat162_rn(v0, v1);
    }
}

// ---------------- mask fp32 -> bf16 pairs ------------------------------------
__global__ __launch_bounds__(256) void mask_cvt_k(const float* __restrict__ mask) {
    size_t i = (size_t)blockIdx.x * 256 + threadIdx.x;
    const size_t n = (size_t)NB * NWIN * NTOK * (NTOK/2);
    if (i < n) {
        float2 v = ((const float2*)mask)[i];
        g_mask_bf[i] = __floats2bfloat162_rn(v.x, v.y);
    }
}

// ====================== tf32 tensor-core GEMM (128x64 tile) ===================
// Double-buffered smem, ONE __syncthreads per k-chunk; R9 scalar gathers.
#define KPAD 36
#define GA_SZ (128*KPAD)
#define GB_SZ (64*KPAD)
#define G_SMEM_B ((2*GA_SZ + 2*GB_SZ) * 4)   /* 55296 bytes */

struct FragC { float c[2][4][4]; };  // [fm][fn][4]

__device__ __forceinline__ void gemm_tile_tf32(
    const float* __restrict__ X, const float* __restrict__ W,
    int bm, int bn, FragC& fc, float* gsm)
{
    const int t    = threadIdx.x;
    const int lane = t & 31;
    const int warp = t >> 5;
    const int wm   = warp & 3;
    const int wn   = warp >> 2;
    const int g    = lane >> 2;
    const int tg   = lane & 3;

    #pragma unroll
    for (int fm = 0; fm < 2; fm++)
        #pragma unroll
        for (int fn = 0; fn < 4; fn++)
            #pragma unroll
            for (int i = 0; i < 4; i++) fc.c[fm][fn][i] = 0.f;

    const int arow = t >> 1;
    const int acol = (t & 1) * 16;
    const int brow = t >> 2;
    const int bcol = (t & 3) * 8;

    const float* Xb = X + (size_t)(bm + arow) * NC + acol;
    const float* Wb = W + (size_t)(bn + brow) * NC + bcol;

    float4 pa[4], pb[2];
    #pragma unroll
    for (int i = 0; i < 4; i++) pa[i] = *(const float4*)(Xb + i * 4);
    #pragma unroll
    for (int i = 0; i < 2; i++) pb[i] = *(const float4*)(Wb + i * 4);

    // store prefetched chunk into buffer b
    auto store_chunk = [&](int b) {
        float* As = gsm + b * GA_SZ;
        float* Bs = gsm + 2 * GA_SZ + b * GB_SZ;
        #pragma unroll
        for (int i = 0; i < 4; i++) {
            uint32_t* d = (uint32_t*)(As + arow * KPAD + acol + i * 4);
            d[0] = f2tf32(pa[i].x); d[1] = f2tf32(pa[i].y);
            d[2] = f2tf32(pa[i].z); d[3] = f2tf32(pa[i].w);
        }
        #pragma unroll
        for (int i = 0; i < 2; i++) {
            uint32_t* d = (uint32_t*)(Bs + brow * KPAD + bcol + i * 4);
            d[0] = f2tf32(pb[i].x); d[1] = f2tf32(pb[i].y);
            d[2] = f2tf32(pb[i].z); d[3] = f2tf32(pb[i].w);
        }
    };

    store_chunk(0);

    for (int c = 0; c < 6; c++) {
        __syncthreads();
        const float* As = gsm + (c & 1) * GA_SZ;
        const float* Bs = gsm + 2 * GA_SZ + (c & 1) * GB_SZ;

        if (c < 5) {
            #pragma unroll
            for (int i = 0; i < 4; i++) pa[i] = *(const float4*)(Xb + (c + 1) * 32 + i * 4);
            #pragma unroll
            for (int i = 0; i < 2; i++) pb[i] = *(const float4*)(Wb + (c + 1) * 32 + i * 4);
        }

        #pragma unroll
        for (int kk = 0; kk < 4; kk++) {
            const int kb = kk * 8;
            uint32_t a[2][4], b[4][2];
            #pragma unroll
            for (int fm = 0; fm < 2; fm++) {
                const int r = wm * 32 + fm * 16 + g;
                const uint32_t* A0 = (const uint32_t*)(As + r * KPAD);
                const uint32_t* A8 = (const uint32_t*)(As + (r + 8) * KPAD);
                a[fm][0] = A0[kb + tg];
                a[fm][1] = A8[kb + tg];
                a[fm][2] = A0[kb + tg + 4];
                a[fm][3] = A8[kb + tg + 4];
            }
            #pragma unroll
            for (int fn = 0; fn < 4; fn++) {
                const uint32_t* B0 = (const uint32_t*)(Bs + (wn * 32 + fn * 8 + g) * KPAD);
                b[fn][0] = B0[kb + tg];
                b[fn][1] = B0[kb + tg + 4];
            }
            #pragma unroll
            for (int fm = 0; fm < 2; fm++)
                #pragma unroll
                for (int fn = 0; fn < 4; fn++)
                    mma_tf32(fc.c[fm][fn], a[fm][0], a[fm][1], a[fm][2], a[fm][3],
                             b[fn][0], b[fn][1]);
        }

        if (c < 5) store_chunk((c + 1) & 1);
    }
}

// ---------------- QKV GEMM + scatter epilogue (q pre-scaled) -----------------
__global__ __launch_bounds__(256) void qkv_gemm_k(
    const float* __restrict__ X, const float* __restrict__ W,
    const float* __restrict__ bias)
{
    extern __shared__ float gsm[];
    const int bm = blockIdx.y * 128;
    const int bn = blockIdx.x * 64;

    FragC fc;
    gemm_tile_tf32(X, W, bm, bn, fc, gsm);

    const int lane = threadIdx.x & 31;
    const int warp = threadIdx.x >> 5;
    const int wm = warp & 3, wn = warp >> 2;
    const int g = lane >> 2, tg = lane & 3;
    const float scale = 0.17677669529663687f;  // 1/sqrt(32)

    #pragma unroll
    for (int fm = 0; fm < 2; fm++) {
        #pragma unroll
        for (int i = 0; i < 2; i++) {
            const int row  = bm + wm * 32 + fm * 16 + g + i * 8;
            const int bidx = row / (NTOK * NWIN);
            const int rem  = row - bidx * (NTOK * NWIN);
            const int w    = rem / NTOK;
            const int n    = rem - w * NTOK;
            #pragma unroll
            for (int fn = 0; fn < 4; fn++) {
                const int col  = bn + wn * 32 + fn * 8 + 2 * tg;
                const int part = col / NC;
                const int c    = col - part * NC;
                const int h    = c >> 5, l = c & 31;
                float* buf = (part == 0) ? g_q : (part == 1) ? g_k : g_v;
                size_t dst = ((((size_t)(bidx * NH + h) * NWIN + w) * NTOK + n) << 5) + l;
                float2 v2 = make_float2(fc.c[fm][fn][2 * i]     + bias[col],
                                        fc.c[fm][fn][2 * i + 1] + bias[col + 1]);
                if (part == 0) { v2.x *= scale; v2.y *= scale; }
                *(float2*)(buf + dst) = v2;
            }
        }
    }
}

// ---------------- projection GEMM --------------------------------------------
__global__ __launch_bounds__(256) void proj_gemm_k(
    const float* __restrict__ W, const float* __restrict__ bias,
    float* __restrict__ out)
{
    extern __shared__ float gsm[];
    const int bm = blockIdx.y * 128;
    const int bn = blockIdx.x * 64;

    FragC fc;
    gemm_tile_tf32(g_attn, W, bm, bn, fc, gsm);

    const int lane = threadIdx.x & 31;
    const int warp = threadIdx.x >> 5;
    const int wm = warp & 3, wn = warp >> 2;
    const int g = lane >> 2, tg = lane & 3;

    #pragma unroll
    for (int fm = 0; fm < 2; fm++) {
        #pragma unroll
        for (int i = 0; i < 2; i++) {
            const int row = bm + wm * 32 + fm * 16 + g + i * 8;
            #pragma unroll
            for (int fn = 0; fn < 4; fn++) {
                const int col = bn + wn * 32 + fn * 8 + 2 * tg;
                float2 v2 = make_float2(fc.c[fm][fn][2 * i]     + bias[col],
                                        fc.c[fm][fn][2 * i + 1] + bias[col + 1]);
                *(float2*)(out + (size_t)row * NC + col) = v2;
            }
        }
    }
}

// ================= tensor-core attention: CTA per (window, head) =============
// 9 warps; warp w owns query rows [16w, 16w+16). Exact one-pass softmax.
// NO P smem (intra-quad shuffle permutation). Bias+mask read as bf16 pairs
// (56 MB combined -> L2-resident).
#define A_OFF_VT  0
#define A_OFF_Q   4736
#define A_OFF_K   (4736 + 5184)
#define A_SMEM_B  ((4736 + 5184 + 5184) * 4)   /* 60416 bytes */

__global__ __launch_bounds__(288, 2) void attn_k(const float* __restrict__ mask) {
    extern __shared__ float sm[];
    float* sVt  = sm + A_OFF_VT;
    float* sQ   = sm + A_OFF_Q;
    float* sK   = sm + A_OFF_K;

    const int bx = blockIdx.x;          // bw * 6 + h
    const int h  = bx % NH;
    const int bw = bx / NH;
    const int b_ = bw >> 6;
    const int w  = bw & 63;
    const int t  = threadIdx.x;
    const int lane = t & 31, warp = t >> 5;
    const int g = lane >> 2, tg = lane & 3;

    const size_t off = (((size_t)(b_ * NH + h) * NWIN + w) * NTOK) << 5;

    // ---- load Q,K (row-major tf32, pad 36) and V transposed (pitch 148) ----
    {
        const float4* qg = (const float4*)(g_q + off);
        const float4* kg = (const float4*)(g_k + off);
        const float4* vg = (const float4*)(g_v + off);
        for (int i = t; i < NTOK * NL / 4; i += 288) {
            int row = i >> 3, c4 = (i & 7) * 4;
            float4 q4 = qg[i];
            uint32_t* dq = (uint32_t*)(sQ + row * 36 + c4);
            dq[0] = f2tf32(q4.x); dq[1] = f2tf32(q4.y);
            dq[2] = f2tf32(q4.z); dq[3] = f2tf32(q4.w);
            float4 k4 = kg[i];
            uint32_t* dk = (uint32_t*)(sK + row * 36 + c4);
            dk[0] = f2tf32(k4.x); dk[1] = f2tf32(k4.y);
            dk[2] = f2tf32(k4.z); dk[3] = f2tf32(k4.w);
            float4 v4 = vg[i];
            uint32_t* dv = (uint32_t*)sVt;
            dv[(c4 + 0) * 148 + row] = f2tf32(v4.x);
            dv[(c4 + 1) * 148 + row] = f2tf32(v4.y);
            dv[(c4 + 2) * 148 + row] = f2tf32(v4.z);
            dv[(c4 + 3) * 148 + row] = f2tf32(v4.w);
        }
    }
    __syncthreads();

    const int r0 = warp * 16 + g;       // rows r0 (c0,c1) and r0+8 (c2,c3)
    const int r1 = r0 + 8;

    // ---- S = Q @ K^T (18 n-tiles x 4 k-steps) ----
    float s[18][4];
    #pragma unroll
    for (int n = 0; n < 18; n++)
        #pragma unroll
        for (int i = 0; i < 4; i++) s[n][i] = 0.f;

    #pragma unroll
    for (int kk = 0; kk < 4; kk++) {
        const int kb = kk * 8;
        uint32_t a0 = *(const uint32_t*)(sQ + r0 * 36 + kb + tg);
        uint32_t a1 = *(const uint32_t*)(sQ + r1 * 36 + kb + tg);
        uint32_t a2 = *(const uint32_t*)(sQ + r0 * 36 + kb + tg + 4);
        uint32_t a3 = *(const uint32_t*)(sQ + r1 * 36 + kb + tg + 4);
        #pragma unroll
        for (int n = 0; n < 18; n++) {
            uint32_t b0 = *(const uint32_t*)(sK + (n * 8 + g) * 36 + kb + tg);
            uint32_t b1 = *(const uint32_t*)(sK + (n * 8 + g) * 36 + kb + tg + 4);
            mma_tf32(s[n], a0, a1, a2, a3, b0, b1);
        }
    }

    // ---- + bias + mask (bf16 pairs, coalesced, L2-resident), row max ----
    const __nv_bfloat162* bf0 = g_bias_full + ((size_t)(w * NH + h) * NTOK + r0) * (NTOK/2);
    const __nv_bfloat162* bf1 = bf0 + 8 * (NTOK/2);
    const __nv_bfloat162* m0  = g_mask_bf + ((size_t)bw * NTOK + r0) * (NTOK/2);
    const __nv_bfloat162* m1  = m0 + 8 * (NTOK/2);

    float mx0 = -1e30f, mx1 = -1e30f;
    #pragma unroll
    for (int n = 0; n < 18; n++) {
        const int p = n * 4 + tg;
        float2 mk0 = __bfloat1622float2(m0[p]);
        float2 mk1 = __bfloat1622float2(m1[p]);
        float2 bb0 = __bfloat1622float2(bf0[p]);
        float2 bb1 = __bfloat1622float2(bf1[p]);
        s[n][0] += bb0.x + mk0.x;
        s[n][1] += bb0.y + mk0.y;
        s[n][2] += bb1.x + mk1.x;
        s[n][3] += bb1.y + mk1.y;
        mx0 = fmaxf(mx0, fmaxf(s[n][0], s[n][1]));
        mx1 = fmaxf(mx1, fmaxf(s[n][2], s[n][3]));
    }
    mx0 = fmaxf(mx0, __shfl_xor_sync(0xffffffffu, mx0, 1));
    mx0 = fmaxf(mx0, __shfl_xor_sync(0xffffffffu, mx0, 2));
    mx1 = fmaxf(mx1, __shfl_xor_sync(0xffffffffu, mx1, 1));
    mx1 = fmaxf(mx1, __shfl_xor_sync(0xffffffffu, mx1, 2));

    // ---- exp, row sums ----
    float sum0 = 0.f, sum1 = 0.f;
    #pragma unroll
    for (int n = 0; n < 18; n++) {
        s[n][0] = __expf(s[n][0] - mx0);
        s[n][1] = __expf(s[n][1] - mx0);
        s[n][2] = __expf(s[n][2] - mx1);
        s[n][3] = __expf(s[n][3] - mx1);
        sum0 += s[n][0] + s[n][1];
        sum1 += s[n][2] + s[n][3];
    }
    sum0 += __shfl_xor_sync(0xffffffffu, sum0, 1);
    sum0 += __shfl_xor_sync(0xffffffffu, sum0, 2);
    sum1 += __shfl_xor_sync(0xffffffffu, sum1, 1);
    sum1 += __shfl_xor_sync(0xffffffffu, sum1, 2);
    const float inv0 = 1.f / sum0, inv1 = 1.f / sum1;

    // ---- normalize P in registers ----
    #pragma unroll
    for (int n = 0; n < 18; n++) {
        s[n][0] *= inv0;
        s[n][1] *= inv0;
        s[n][2] *= inv1;
        s[n][3] *= inv1;
    }

    // ---- O = P @ V: shuffle C-layout -> A-layout per k-step, no smem P ----
    float o[4][4];
    #pragma unroll
    for (int n = 0; n < 4; n++)
        #pragma unroll
        for (int i = 0; i < 4; i++) o[n][i] = 0.f;

    const int lane_lo = (lane & ~3) | (tg >> 1);
    const bool odd = (tg & 1);

    #pragma unroll
    for (int k = 0; k < 18; k++) {
        float v00 = __shfl_sync(0xffffffffu, s[k][0], lane_lo);
        float v01 = __shfl_sync(0xffffffffu, s[k][1], lane_lo);
        float v20 = __shfl_sync(0xffffffffu, s[k][0], lane_lo + 2);
        float v21 = __shfl_sync(0xffffffffu, s[k][1], lane_lo + 2);
        float v10 = __shfl_sync(0xffffffffu, s[k][2], lane_lo);
        float v11 = __shfl_sync(0xffffffffu, s[k][3], lane_lo);
        float v30 = __shfl_sync(0xffffffffu, s[k][2], lane_lo + 2);
        float v31 = __shfl_sync(0xffffffffu, s[k][3], lane_lo + 2);
        uint32_t a0 = f2tf32(odd ? v01 : v00);
        uint32_t a1 = f2tf32(odd ? v11 : v10);
        uint32_t a2 = f2tf32(odd ? v21 : v20);
        uint32_t a3 = f2tf32(odd ? v31 : v30);

        const int kb = k * 8;
        #pragma unroll
        for (int n = 0; n < 4; n++) {
            uint32_t b0 = *(const uint32_t*)(sVt + (n * 8 + g) * 148 + kb + tg);
            uint32_t b1 = *(const uint32_t*)(sVt + (n * 8 + g) * 148 + kb + tg + 4);
            mma_tf32(o[n], a0, a1, a2, a3, b0, b1);
        }
    }

    // ---- write out (already normalized) ----
    float* ob = g_attn + ((size_t)bw * NTOK) * NC + h * NL;
    #pragma unroll
    for (int n = 0; n < 4; n++) {
        const int c = n * 8 + 2 * tg;
        *(float2*)(ob + (size_t)r0 * NC + c) = make_float2(o[n][0], o[n][1]);
        *(float2*)(ob + (size_t)r1 * NC + c) = make_float2(o[n][2], o[n][3]);
    }
}

// ---------------- launch --------------------------------------------------
extern "C" void kernel_launch(void* const* d_in, const int* in_sizes, int n_in,
                              void* d_out, int out_size)
{
    const float* x          = (const float*)d_in[0];
    const float* mask       = (const float*)d_in[1];
    const float* qkv_w      = (const float*)d_in[2];
    const float* qkv_b      = (const float*)d_in[3];
    const float* proj_w     = (const float*)d_in[4];
    const float* proj_b     = (const float*)d_in[5];
    const float* bias_table = (const float*)d_in[6];
    float* out = (float*)d_out;

    cudaFuncSetAttribute(attn_k, cudaFuncAttributeMaxDynamicSharedMemorySize,
                         A_SMEM_B);
    cudaFuncSetAttribute(qkv_gemm_k, cudaFuncAttributeMaxDynamicSharedMemorySize,
                         G_SMEM_B);
    cudaFuncSetAttribute(proj_gemm_k, cudaFuncAttributeMaxDynamicSharedMemorySize,
                         G_SMEM_B);

    bias_transpose_k<<<(BIAS_E * NWIN * NH + 255) / 256, 256>>>(bias_table);
    bias_expand_k<<<NWIN * NH, 256>>>();
    {
        const size_t npairs = (size_t)NB * NWIN * NTOK * (NTOK/2);
        mask_cvt_k<<<(unsigned)((npairs + 255) / 256), 256>>>(mask);
    }
    qkv_gemm_k<<<dim3(9, MROWS / 128), 256, G_SMEM_B>>>(x, qkv_w, qkv_b);
    attn_k<<<NB * NWIN * NH, 288, A_SMEM_B>>>(mask);
    proj_gemm_k<<<dim3(3, MROWS / 128), 256, G_SMEM_B>>>(proj_w, proj_b, out);
}

// round 15
// speedup vs baseline: 1.2616x; 1.2616x over previous
#include <cuda_runtime.h>
#include <cuda_bf16.h>
#include <cstdint>

#define NB    15
#define NWIN  64
#define NTOK  144
#define NC    192
#define NH    6
#define NL    32
#define MROWS (NB*NWIN*NTOK)   /* 138240 */
#define BIAS_E 3312

// ---------------- scratch (device globals; no allocs allowed) ----------------
__device__ float g_q[(size_t)NB*NH*NWIN*NTOK*NL];      // 106 MB (pre-scaled)
__device__ float g_k[(size_t)NB*NH*NWIN*NTOK*NL];      // 106 MB
__device__ float g_v[(size_t)NB*NH*NWIN*NTOK*NL];      // 106 MB
__device__ float g_attn[(size_t)MROWS*NC];             // 106 MB
__device__ float g_bias_t[(size_t)NWIN*NH*BIAS_E];     // 5 MB, layout (w,h,e)
__device__ __nv_bfloat162 g_bias_full[(size_t)NWIN*NH*NTOK*(NTOK/2)]; // 16 MB
__device__ __nv_bfloat162 g_mask_bf[(size_t)NB*NWIN*NTOK*(NTOK/2)];   // 40 MB

__device__ __forceinline__ uint32_t f2tf32(float x) {
    uint32_t r;
    asm("cvt.rna.tf32.f32 %0, %1;" : "=r"(r) : "f"(x));
    return r;
}

__device__ __forceinline__ void mma_tf32(float c[4], uint32_t a0, uint32_t a1,
                                         uint32_t a2, uint32_t a3,
                                         uint32_t b0, uint32_t b1) {
    asm volatile(
        "mma.sync.aligned.m16n8k8.row.col.f32.tf32.tf32.f32 "
        "{%0,%1,%2,%3}, {%4,%5,%6,%7}, {%8,%9}, {%0,%1,%2,%3};"
        : "+f"(c[0]), "+f"(c[1]), "+f"(c[2]), "+f"(c[3])
        : "r"(a0), "r"(a1), "r"(a2), "r"(a3), "r"(b0), "r"(b1));
}

// ---------------- bias table transpose: (e,w,h) -> (w,h,e) -------------------
__global__ __launch_bounds__(256) void bias_transpose_k(const float* __restrict__ bt) {
    int i = blockIdx.x * 256 + threadIdx.x;
    if (i < BIAS_E * NWIN * NH) {
        int e   = i / (NWIN * NH);
        int rem = i - e * (NWIN * NH);
        int w   = rem / NH;
        int h   = rem - w * NH;
        g_bias_t[(w * NH + h) * BIAS_E + e] = bt[i];
    }
}

// ------------- bias expansion: (w,h,e) -> dense bf16 (w,h,n,m) ---------------
__global__ __launch_bounds__(256) void bias_expand_k() {
    __shared__ int moff[NTOK];
    const int wh = blockIdx.x;              // w * NH + h
    const int t  = threadIdx.x;
    if (t < NTOK) {
        int zm = t / 72, r = t - zm * 72, hm = r / 12, wm = r - hm * 12;
        moff[t] = 1656 * zm + 138 * hm - wm;
    }
    __syncthreads();
    const float* bt = g_bias_t + (size_t)wh * BIAS_E;
    __nv_bfloat162* dst = g_bias_full + (size_t)wh * (NTOK * (NTOK/2));
    for (int i = t; i < NTOK * (NTOK/2); i += 256) {
        const int n  = i / (NTOK/2);
        const int m2 = (i - n * (NTOK/2)) * 2;
        int zn = n / 72, rn = n - zn * 72, hn = rn / 12, wn = rn - hn * 12;
        const int base = 828 * zn + 23 * hn + wn + 11;
        float v0 = __ldg(bt + base + moff[m2]);
        float v1 = __ldg(bt + base + moff[m2 + 1]);
        dst[i] = __floats2bfloat162_rn(v0, v1);
    }
}

// ---------------- mask fp32 -> bf16 pairs ------------------------------------
__global__ __launch_bounds__(256) void mask_cvt_k(const float* __restrict__ mask) {
    size_t i = (size_t)blockIdx.x * 256 + threadIdx.x;
    const size_t n = (size_t)NB * NWIN * NTOK * (NTOK/2);
    if (i < n) {
        float2 v = ((const float2*)mask)[i];
        g_mask_bf[i] = __floats2bfloat162_rn(v.x, v.y);
    }
}

// ====================== tf32 tensor-core GEMM (128x64 tile) ===================
// R9-proven version: static smem, scalar fragment gathers, reg-lean.
#define KPAD 36

struct FragC { float c[2][4][4]; };  // [fm][fn][4]

__device__ __forceinline__ void gemm_tile_tf32(
    const float* __restrict__ X, const float* __restrict__ W,
    int bm, int bn, FragC& fc,
    float (*As)[KPAD], float (*Bs)[KPAD])
{
    const int t    = threadIdx.x;
    const int lane = t & 31;
    const int warp = t >> 5;
    const int wm   = warp & 3;
    const int wn   = warp >> 2;
    const int g    = lane >> 2;
    const int tg   = lane & 3;

    #pragma unroll
    for (int fm = 0; fm < 2; fm++)
        #pragma unroll
        for (int fn = 0; fn < 4; fn++)
            #pragma unroll
            for (int i = 0; i < 4; i++) fc.c[fm][fn][i] = 0.f;

    const int arow = t >> 1;
    const int acol = (t & 1) * 16;
    const int brow = t >> 2;
    const int bcol = (t & 3) * 8;

    const float* Xb = X + (size_t)(bm + arow) * NC + acol;
    const float* Wb = W + (size_t)(bn + brow) * NC + bcol;

    float4 pa[4], pb[2];
    #pragma unroll
    for (int i = 0; i < 4; i++) pa[i] = *(const float4*)(Xb + i * 4);
    #pragma unroll
    for (int i = 0; i < 2; i++) pb[i] = *(const float4*)(Wb + i * 4);

    for (int kc = 0; kc < NC; kc += 32) {
        #pragma unroll
        for (int i = 0; i < 4; i++) {
            uint32_t* d = (uint32_t*)&As[arow][acol + i * 4];
            d[0] = f2tf32(pa[i].x); d[1] = f2tf32(pa[i].y);
            d[2] = f2tf32(pa[i].z); d[3] = f2tf32(pa[i].w);
        }
        #pragma unroll
        for (int i = 0; i < 2; i++) {
            uint32_t* d = (uint32_t*)&Bs[brow][bcol + i * 4];
            d[0] = f2tf32(pb[i].x); d[1] = f2tf32(pb[i].y);
            d[2] = f2tf32(pb[i].z); d[3] = f2tf32(pb[i].w);
        }
        __syncthreads();

        if (kc + 32 < NC) {
            #pragma unroll
            for (int i = 0; i < 4; i++) pa[i] = *(const float4*)(Xb + kc + 32 + i * 4);
            #pragma unroll
            for (int i = 0; i < 2; i++) pb[i] = *(const float4*)(Wb + kc + 32 + i * 4);
        }

        #pragma unroll
        for (int kk = 0; kk < 4; kk++) {
            const int kb = kk * 8;
            uint32_t a[2][4], b[4][2];
            #pragma unroll
            for (int fm = 0; fm < 2; fm++) {
                const int r = wm * 32 + fm * 16 + g;
                const uint32_t* A0 = (const uint32_t*)As[r];
                const uint32_t* A8 = (const uint32_t*)As[r + 8];
                a[fm][0] = A0[kb + tg];
                a[fm][1] = A8[kb + tg];
                a[fm][2] = A0[kb + tg + 4];
                a[fm][3] = A8[kb + tg + 4];
            }
            #pragma unroll
            for (int fn = 0; fn < 4; fn++) {
                const uint32_t* B0 = (const uint32_t*)Bs[wn * 32 + fn * 8 + g];
                b[fn][0] = B0[kb + tg];
                b[fn][1] = B0[kb + tg + 4];
            }
            #pragma unroll
            for (int fm = 0; fm < 2; fm++)
                #pragma unroll
                for (int fn = 0; fn < 4; fn++)
                    mma_tf32(fc.c[fm][fn], a[fm][0], a[fm][1], a[fm][2], a[fm][3],
                             b[fn][0], b[fn][1]);
        }
        __syncthreads();
    }
}

// ---------------- QKV GEMM + scatter epilogue (q pre-scaled) -----------------
__global__ __launch_bounds__(256) void qkv_gemm_k(
    const float* __restrict__ X, const float* __restrict__ W,
    const float* __restrict__ bias)
{
    __shared__ float As[128][KPAD];
    __shared__ float Bs[64][KPAD];
    const int bm = blockIdx.y * 128;
    const int bn = blockIdx.x * 64;

    FragC fc;
    gemm_tile_tf32(X, W, bm, bn, fc, As, Bs);

    const int lane = threadIdx.x & 31;
    const int warp = threadIdx.x >> 5;
    const int wm = warp & 3, wn = warp >> 2;
    const int g = lane >> 2, tg = lane & 3;
    const float scale = 0.17677669529663687f;  // 1/sqrt(32)

    #pragma unroll
    for (int fm = 0; fm < 2; fm++) {
        #pragma unroll
        for (int i = 0; i < 2; i++) {
            const int row  = bm + wm * 32 + fm * 16 + g + i * 8;
            const int bidx = row / (NTOK * NWIN);
            const int rem  = row - bidx * (NTOK * NWIN);
            const int w    = rem / NTOK;
            const int n    = rem - w * NTOK;
            #pragma unroll
            for (int fn = 0; fn < 4; fn++) {
                const int col  = bn + wn * 32 + fn * 8 + 2 * tg;
                const int part = col / NC;
                const int c    = col - part * NC;
                const int h    = c >> 5, l = c & 31;
                float* buf = (part == 0) ? g_q : (part == 1) ? g_k : g_v;
                size_t dst = ((((size_t)(bidx * NH + h) * NWIN + w) * NTOK + n) << 5) + l;
                float2 v2 = make_float2(fc.c[fm][fn][2 * i]     + bias[col],
                                        fc.c[fm][fn][2 * i + 1] + bias[col + 1]);
                if (part == 0) { v2.x *= scale; v2.y *= scale; }
                *(float2*)(buf + dst) = v2;
            }
        }
    }
}

// ---------------- projection GEMM --------------------------------------------
__global__ __launch_bounds__(256) void proj_gemm_k(
    const float* __restrict__ W, const float* __restrict__ bias,
    float* __restrict__ out)
{
    __shared__ float As[128][KPAD];
    __shared__ float Bs[64][KPAD];
    const int bm = blockIdx.y * 128;
    const int bn = blockIdx.x * 64;

    FragC fc;
    gemm_tile_tf32(g_attn, W, bm, bn, fc, As, Bs);

    const int lane = threadIdx.x & 31;
    const int warp = threadIdx.x >> 5;
    const int wm = warp & 3, wn = warp >> 2;
    const int g = lane >> 2, tg = lane & 3;

    #pragma unroll
    for (int fm = 0; fm < 2; fm++) {
        #pragma unroll
        for (int i = 0; i < 2; i++) {
            const int row = bm + wm * 32 + fm * 16 + g + i * 8;
            #pragma unroll
            for (int fn = 0; fn < 4; fn++) {
                const int col = bn + wn * 32 + fn * 8 + 2 * tg;
                float2 v2 = make_float2(fc.c[fm][fn][2 * i]     + bias[col],
                                        fc.c[fm][fn][2 * i + 1] + bias[col + 1]);
                *(float2*)(out + (size_t)row * NC + col) = v2;
            }
        }
    }
}

// ================= tensor-core attention: CTA per (window, head) =============
// 9 warps; warp w owns query rows [16w, 16w+16). Exact one-pass softmax.
// QK loop is n-outer / kk-inner with the bias+mask bf16 LDGs issued at the
// top of each n-iteration -> load latency overlaps MMA issue. No P smem
// (intra-quad shuffle permutation). 60.4 KB smem -> 2 CTAs/SM.
#define A_OFF_VT  0
#define A_OFF_Q   4736
#define A_OFF_K   (4736 + 5184)
#define A_SMEM_B  ((4736 + 5184 + 5184) * 4)   /* 60416 bytes */

__global__ __launch_bounds__(288, 2) void attn_k(const float* __restrict__ mask) {
    extern __shared__ float sm[];
    float* sVt  = sm + A_OFF_VT;
    float* sQ   = sm + A_OFF_Q;
    float* sK   = sm + A_OFF_K;

    const int bx = blockIdx.x;          // bw * 6 + h
    const int h  = bx % NH;
    const int bw = bx / NH;
    const int b_ = bw >> 6;
    const int w  = bw & 63;
    const int t  = threadIdx.x;
    const int lane = t & 31, warp = t >> 5;
    const int g = lane >> 2, tg = lane & 3;

    const size_t off = (((size_t)(b_ * NH + h) * NWIN + w) * NTOK) << 5;

    // ---- load Q,K (row-major tf32, pad 36) and V transposed (pitch 148) ----
    {
        const float4* qg = (const float4*)(g_q + off);
        const float4* kg = (const float4*)(g_k + off);
        const float4* vg = (const float4*)(g_v + off);
        for (int i = t; i < NTOK * NL / 4; i += 288) {
            int row = i >> 3, c4 = (i & 7) * 4;
            float4 q4 = qg[i];
            uint32_t* dq = (uint32_t*)(sQ + row * 36 + c4);
            dq[0] = f2tf32(q4.x); dq[1] = f2tf32(q4.y);
            dq[2] = f2tf32(q4.z); dq[3] = f2tf32(q4.w);
            float4 k4 = kg[i];
            uint32_t* dk = (uint32_t*)(sK + row * 36 + c4);
            dk[0] = f2tf32(k4.x); dk[1] = f2tf32(k4.y);
            dk[2] = f2tf32(k4.z); dk[3] = f2tf32(k4.w);
            float4 v4 = vg[i];
            uint32_t* dv = (uint32_t*)sVt;
            dv[(c4 + 0) * 148 + row] = f2tf32(v4.x);
            dv[(c4 + 1) * 148 + row] = f2tf32(v4.y);
            dv[(c4 + 2) * 148 + row] = f2tf32(v4.z);
            dv[(c4 + 3) * 148 + row] = f2tf32(v4.w);
        }
    }
    __syncthreads();

    const int r0 = warp * 16 + g;       // rows r0 (c0,c1) and r0+8 (c2,c3)
    const int r1 = r0 + 8;

    // ---- A fragments for all 4 kk-steps (hoisted once) ----
    uint32_t aq[4][4];
    #pragma unroll
    for (int kk = 0; kk < 4; kk++) {
        const int kb = kk * 8;
        aq[kk][0] = *(const uint32_t*)(sQ + r0 * 36 + kb + tg);
        aq[kk][1] = *(const uint32_t*)(sQ + r1 * 36 + kb + tg);
        aq[kk][2] = *(const uint32_t*)(sQ + r0 * 36 + kb + tg + 4);
        aq[kk][3] = *(const uint32_t*)(sQ + r1 * 36 + kb + tg + 4);
    }

    const __nv_bfloat162* bf0 = g_bias_full + ((size_t)(w * NH + h) * NTOK + r0) * (NTOK/2);
    const __nv_bfloat162* bf1 = bf0 + 8 * (NTOK/2);
    const __nv_bfloat162* m0  = g_mask_bf + ((size_t)bw * NTOK + r0) * (NTOK/2);
    const __nv_bfloat162* m1  = m0 + 8 * (NTOK/2);

    // ---- S = Q@K^T, n-outer: per-tile LDG (bias/mask) overlaps MMAs ----
    float s[18][4];
    float mx0 = -1e30f, mx1 = -1e30f;
    #pragma unroll
    for (int n = 0; n < 18; n++) {
        const int p = n * 4 + tg;
        __nv_bfloat162 xb0 = bf0[p];
        __nv_bfloat162 xb1 = bf1[p];
        __nv_bfloat162 xm0 = m0[p];
        __nv_bfloat162 xm1 = m1[p];

        s[n][0] = 0.f; s[n][1] = 0.f; s[n][2] = 0.f; s[n][3] = 0.f;
        #pragma unroll
        for (int kk = 0; kk < 4; kk++) {
            const int kb = kk * 8;
            uint32_t b0 = *(const uint32_t*)(sK + (n * 8 + g) * 36 + kb + tg);
            uint32_t b1 = *(const uint32_t*)(sK + (n * 8 + g) * 36 + kb + tg + 4);
            mma_tf32(s[n], aq[kk][0], aq[kk][1], aq[kk][2], aq[kk][3], b0, b1);
        }

        float2 bb0 = __bfloat1622float2(xb0);
        float2 bb1 = __bfloat1622float2(xb1);
        float2 mk0 = __bfloat1622float2(xm0);
        float2 mk1 = __bfloat1622float2(xm1);
        s[n][0] += bb0.x + mk0.x;
        s[n][1] += bb0.y + mk0.y;
        s[n][2] += bb1.x + mk1.x;
        s[n][3] += bb1.y + mk1.y;
        mx0 = fmaxf(mx0, fmaxf(s[n][0], s[n][1]));
        mx1 = fmaxf(mx1, fmaxf(s[n][2], s[n][3]));
    }
    mx0 = fmaxf(mx0, __shfl_xor_sync(0xffffffffu, mx0, 1));
    mx0 = fmaxf(mx0, __shfl_xor_sync(0xffffffffu, mx0, 2));
    mx1 = fmaxf(mx1, __shfl_xor_sync(0xffffffffu, mx1, 1));
    mx1 = fmaxf(mx1, __shfl_xor_sync(0xffffffffu, mx1, 2));

    // ---- exp, row sums ----
    float sum0 = 0.f, sum1 = 0.f;
    #pragma unroll
    for (int n = 0; n < 18; n++) {
        s[n][0] = __expf(s[n][0] - mx0);
        s[n][1] = __expf(s[n][1] - mx0);
        s[n][2] = __expf(s[n][2] - mx1);
        s[n][3] = __expf(s[n][3] - mx1);
        sum0 += s[n][0] + s[n][1];
        sum1 += s[n][2] + s[n][3];
    }
    sum0 += __shfl_xor_sync(0xffffffffu, sum0, 1);
    sum0 += __shfl_xor_sync(0xffffffffu, sum0, 2);
    sum1 += __shfl_xor_sync(0xffffffffu, sum1, 1);
    sum1 += __shfl_xor_sync(0xffffffffu, sum1, 2);
    const float inv0 = 1.f / sum0, inv1 = 1.f / sum1;

    // ---- normalize P in registers ----
    #pragma unroll
    for (int n = 0; n < 18; n++) {
        s[n][0] *= inv0;
        s[n][1] *= inv0;
        s[n][2] *= inv1;
        s[n][3] *= inv1;
    }

    // ---- O = P @ V: shuffle C-layout -> A-layout per k-step, no smem P ----
    float o[4][4];
    #pragma unroll
    for (int n = 0; n < 4; n++)
        #pragma unroll
        for (int i = 0; i < 4; i++) o[n][i] = 0.f;

    const int lane_lo = (lane & ~3) | (tg >> 1);
    const bool odd = (tg & 1);

    #pragma unroll
    for (int k = 0; k < 18; k++) {
        float v00 = __shfl_sync(0xffffffffu, s[k][0], lane_lo);
        float v01 = __shfl_sync(0xffffffffu, s[k][1], lane_lo);
        float v20 = __shfl_sync(0xffffffffu, s[k][0], lane_lo + 2);
        float v21 = __shfl_sync(0xffffffffu, s[k][1], lane_lo + 2);
        float v10 = __shfl_sync(0xffffffffu, s[k][2], lane_lo);
        float v11 = __shfl_sync(0xffffffffu, s[k][3], lane_lo);
        float v30 = __shfl_sync(0xffffffffu, s[k][2], lane_lo + 2);
        float v31 = __shfl_sync(0xffffffffu, s[k][3], lane_lo + 2);
        uint32_t a0 = f2tf32(odd ? v01 : v00);
        uint32_t a1 = f2tf32(odd ? v11 : v10);
        uint32_t a2 = f2tf32(odd ? v21 : v20);
        uint32_t a3 = f2tf32(odd ? v31 : v30);

        const int kb = k * 8;
        #pragma unroll
        for (int n = 0; n < 4; n++) {
            uint32_t b0 = *(const uint32_t*)(sVt + (n * 8 + g) * 148 + kb + tg);
            uint32_t b1 = *(const uint32_t*)(sVt + (n * 8 + g) * 148 + kb + tg + 4);
            mma_tf32(o[n], a0, a1, a2, a3, b0, b1);
        }
    }

    // ---- write out (already normalized) ----
    float* ob = g_attn + ((size_t)bw * NTOK) * NC + h * NL;
    #pragma unroll
    for (int n = 0; n < 4; n++) {
        const int c = n * 8 + 2 * tg;
        *(float2*)(ob + (size_t)r0 * NC + c) = make_float2(o[n][0], o[n][1]);
        *(float2*)(ob + (size_t)r1 * NC + c) = make_float2(o[n][2], o[n][3]);
    }
}

// ---------------- launch --------------------------------------------------
extern "C" void kernel_launch(void* const* d_in, const int* in_sizes, int n_in,
                              void* d_out, int out_size)
{
    const float* x          = (const float*)d_in[0];
    const float* mask       = (const float*)d_in[1];
    const float* qkv_w      = (const float*)d_in[2];
    const float* qkv_b      = (const float*)d_in[3];
    const float* proj_w     = (const float*)d_in[4];
    const float* proj_b     = (const float*)d_in[5];
    const float* bias_table = (const float*)d_in[6];
    float* out = (float*)d_out;

    cudaFuncSetAttribute(attn_k, cudaFuncAttributeMaxDynamicSharedMemorySize,
                         A_SMEM_B);

    bias_transpose_k<<<(BIAS_E * NWIN * NH + 255) / 256, 256>>>(bias_table);
    bias_expand_k<<<NWIN * NH, 256>>>();
    {
        const size_t npairs = (size_t)NB * NWIN * NTOK * (NTOK/2);
        mask_cvt_k<<<(unsigned)((npairs + 255) / 256), 256>>>(mask);
    }
    qkv_gemm_k<<<dim3(9, MROWS / 128), 256>>>(x, qkv_w, qkv_b);
    attn_k<<<NB * NWIN * NH, 288, A_SMEM_B>>>(mask);
    proj_gemm_k<<<dim3(3, MROWS / 128), 256>>>(proj_w, proj_b, out);
}